// round 1
// baseline (speedup 1.0000x reference)
#include <cuda_runtime.h>

// SoftNCutsLoss: B=4, K=8, D=H=W=32, radius=4 -> 7^3 window, 251 nonzero offsets.
// out[b] = 8 - sum_k assocA[b,k]/assocV[b,k]
//   assocA[b,k] = sum_p preds[k,p] * sum_off aff(p,off) * preds_pad[k,p+off]
//   assocV[b,k] = sum_p preds[k,p] * sum_off aff(p,off)
//   aff = exp(-(I_p - I_q)^2/100) * exp(-d2/16), d2 = |off|^2 < 16
// Padding value = float64 eps (constant pad in reference).

#define EPSV 2.2204460492503131e-16f
#define NPAD 2744           // 14*14*14
#define SMEM_BYTES ((344 + 2744) * 4 + 4 * 2744 * 8)

__device__ float gAV[64];   // [b][0..7]=assocA, [b][8..15]=assocV

__global__ void zero_kernel() {
    int t = threadIdx.x;
    if (t < 64) gAV[t] = 0.f;
}

__device__ __forceinline__ unsigned long long pack2(float a) {
    unsigned long long r;
    asm("mov.b64 %0, {%1, %1};" : "=l"(r) : "f"(a));
    return r;
}
__device__ __forceinline__ unsigned long long pack2f(float a, float b) {
    unsigned long long r;
    asm("mov.b64 %0, {%1, %2};" : "=l"(r) : "f"(a), "f"(b));
    return r;
}
__device__ __forceinline__ void unpack2(unsigned long long x, float& lo, float& hi) {
    asm("mov.b64 {%0, %1}, %2;" : "=f"(lo), "=f"(hi) : "l"(x));
}
__device__ __forceinline__ void fma2(unsigned long long& acc, unsigned long long a,
                                     unsigned long long b) {
    asm("fma.rn.f32x2 %0, %1, %2, %0;" : "+l"(acc) : "l"(a), "l"(b));
}
__device__ __forceinline__ float ex2(float x) {
    float r;
    asm("ex2.approx.f32 %0, %1;" : "=f"(r) : "f"(x));
    return r;
}

__global__ __launch_bounds__(512, 2)
void soft_ncuts_main(const float* __restrict__ batch, const float* __restrict__ preds) {
    extern __shared__ char smem_raw[];
    float* sW = (float*)smem_raw;                             // 343 (+1 pad) weights
    float* sI = sW + 344;                                     // 2744 intensities
    unsigned long long* sP = (unsigned long long*)(sI + NPAD); // 4 * 2744 float2 (k pairs)

    const int tid = threadIdx.x;
    const int b = blockIdx.y;
    const int tile = blockIdx.x;
    const int oz = (tile & 3) * 8;
    const int oy = ((tile >> 2) & 3) * 8;
    const int ox = (tile >> 4) * 8;

    // spatial gaussian weight table (7^3)
    if (tid < 343) {
        int x = tid / 49;
        int rem = tid - x * 49;
        int y = rem / 7;
        int z = rem - y * 7;
        int dx = x - 3, dy = y - 3, dz = z - 3;
        int d2 = dx * dx + dy * dy + dz * dz;
        sW[tid] = (d2 < 16) ? expf((float)d2 * (-1.f / 16.f)) : 0.f;
    }

    const float* batchb = batch + b * 32768;
    const float* predsb = preds + (b * 8) * 32768;

    // stage padded 14^3 tile; halo outside volume = EPS
    for (int v = tid; v < NPAD; v += 512) {
        int px = v / 196;
        int r = v - px * 196;
        int py = r / 14;
        int pz = r - py * 14;
        int gx = ox + px - 3, gy = oy + py - 3, gz = oz + pz - 3;
        bool inb = ((unsigned)gx < 32u) && ((unsigned)gy < 32u) && ((unsigned)gz < 32u);
        int g = gx * 1024 + gy * 32 + gz;
        sI[v] = inb ? batchb[g] : EPSV;
#pragma unroll
        for (int kk = 0; kk < 4; kk++) {
            float p0 = inb ? predsb[(2 * kk) * 32768 + g] : EPSV;
            float p1 = inb ? predsb[(2 * kk + 1) * 32768 + g] : EPSV;
            sP[kk * NPAD + v] = pack2f(p0, p1);
        }
    }
    __syncthreads();

    const int lz = tid & 7, ly = (tid >> 3) & 7, lx = tid >> 6;
    const int v0 = (lx + 3) * 196 + (ly + 3) * 14 + (lz + 3);
    const float I = sI[v0];

    unsigned long long acc0 = 0ull, acc1 = 0ull, acc2 = 0ull, acc3 = 0ull;
    float sumw = 0.f;
    const float K2 = -0.014426950408889634f;  // -log2(e)/100

    for (int dx = -3; dx <= 3; dx++) {
        int rx = 16 - dx * dx;
        for (int dy = -3; dy <= 3; dy++) {
            int r2 = rx - dy * dy;
            int m;
            if (r2 >= 10) m = 3;
            else if (r2 >= 5) m = 2;
            else if (r2 >= 2) m = 1;
            else if (r2 >= 1) m = 0;
            else continue;
            int vb = v0 + dx * 196 + dy * 14;
            int wb = ((dx + 3) * 7 + (dy + 3)) * 7 + 3;
            for (int dz = -m; dz <= m; dz++) {
                float w = sW[wb + dz];            // broadcast
                int v = vb + dz;
                float d = I - sI[v];
                float a = w * ex2(d * d * K2);    // exp(-(d^2)/100) * w
                sumw += a;
                unsigned long long a2 = pack2(a);
                fma2(acc0, a2, sP[v]);
                fma2(acc1, a2, sP[NPAD + v]);
                fma2(acc2, a2, sP[2 * NPAD + v]);
                fma2(acc3, a2, sP[3 * NPAD + v]);
            }
        }
    }

    // per-thread contributions: A_k = preds[k,p]*numer[k], V_k = preds[k,p]*sumw
    float qf[8], ac[8];
    unpack2(sP[v0], qf[0], qf[1]);
    unpack2(sP[NPAD + v0], qf[2], qf[3]);
    unpack2(sP[2 * NPAD + v0], qf[4], qf[5]);
    unpack2(sP[3 * NPAD + v0], qf[6], qf[7]);
    unpack2(acc0, ac[0], ac[1]);
    unpack2(acc1, ac[2], ac[3]);
    unpack2(acc2, ac[4], ac[5]);
    unpack2(acc3, ac[6], ac[7]);

    float c[16];
#pragma unroll
    for (int k = 0; k < 8; k++) {
        c[k] = ac[k] * qf[k];
        c[8 + k] = sumw * qf[k];
    }

    __shared__ float sRed[16];
    if (tid < 16) sRed[tid] = 0.f;
    __syncthreads();
#pragma unroll
    for (int j = 0; j < 16; j++) {
        float val = c[j];
#pragma unroll
        for (int o = 16; o; o >>= 1) val += __shfl_xor_sync(0xffffffffu, val, o);
        if ((tid & 31) == 0) atomicAdd(&sRed[j], val);
    }
    __syncthreads();
    if (tid < 16) atomicAdd(&gAV[b * 16 + tid], sRed[tid]);
}

__global__ void finalize_kernel(float* __restrict__ out) {
    int b = threadIdx.x;
    if (b < 4) {
        float s = 0.f;
#pragma unroll
        for (int k = 0; k < 8; k++) s += gAV[b * 16 + k] / gAV[b * 16 + 8 + k];
        out[b] = 8.f - s;
    }
}

extern "C" void kernel_launch(void* const* d_in, const int* in_sizes, int n_in,
                              void* d_out, int out_size) {
    const float* batch = (const float*)d_in[0];
    const float* preds = (const float*)d_in[1];
    float* out = (float*)d_out;

    cudaFuncSetAttribute(soft_ncuts_main, cudaFuncAttributeMaxDynamicSharedMemorySize,
                         SMEM_BYTES);

    zero_kernel<<<1, 64>>>();
    dim3 grid(64, 4);
    soft_ncuts_main<<<grid, 512, SMEM_BYTES>>>(batch, preds);
    finalize_kernel<<<1, 32>>>(out);
}

// round 3
// speedup vs baseline: 1.9993x; 1.9993x over previous
#include <cuda_runtime.h>

// SoftNCutsLoss: B=4, K=8, 32^3, radius 4 -> 251 nonzero window offsets.
// Tile 4x4x32 (z = full extent), 512 threads, warp = 32 consecutive z.
// Preds in smem as bf16 pairs (2 x LDS.64 per offset), intensity fp32.
// aff = ex2(dI^2*K2 + d2*K3); K2=-log2e/100, K3=-log2e/16.

#define EPSV 2.2204460492503131e-16f
#define TPX 10
#define TPY 10
#define TPZ 38
#define NPAD (TPX * TPY * TPZ)      // 3800
#define SMEM_BYTES (NPAD * 8 * 2 + NPAD * 4)

typedef unsigned long long ull;

__device__ float gPart[256 * 16];   // per-CTA partials: [cta][0..7]=A, [8..15]=V

// -------- row table: offsets grouped by dz-extent (m=3: 21, m=2: 16, m=1: 8) --------
struct RowTab {
    int   off[45];
    float c[45];
};
__host__ __device__ constexpr RowTab make_rows() {
    RowTab t{};
    const float K3 = -0.09016844005556021f;  // -log2(e)/16
    int idx = 0;
    for (int want = 3; want >= 1; want--) {
        for (int dx = -3; dx <= 3; dx++)
            for (int dy = -3; dy <= 3; dy++) {
                int r2 = 16 - dx * dx - dy * dy;
                int m = 0;
                if (r2 >= 10) m = 3;
                else if (r2 >= 5) m = 2;
                else if (r2 >= 2) m = 1;
                else continue;
                if (m != want) continue;
                t.off[idx] = dx * (TPY * TPZ) + dy * TPZ;
                t.c[idx] = (float)(dx * dx + dy * dy) * K3;
                idx++;
            }
    }
    return t;
}
__constant__ RowTab ROWS = make_rows();

__device__ __forceinline__ ull pack2(float a) {
    ull r; asm("mov.b64 %0, {%1, %1};" : "=l"(r) : "f"(a)); return r;
}
__device__ __forceinline__ void unpack2(ull x, float& lo, float& hi) {
    asm("mov.b64 {%0, %1}, %2;" : "=f"(lo), "=f"(hi) : "l"(x));
}
__device__ __forceinline__ void fma2(ull& acc, ull a, ull b) {
    asm("fma.rn.f32x2 %0, %1, %2, %0;" : "+l"(acc) : "l"(a), "l"(b));
}
__device__ __forceinline__ float ex2(float x) {
    float r; asm("ex2.approx.f32 %0, %1;" : "=f"(r) : "f"(x)); return r;
}
__device__ __forceinline__ unsigned cvt_bf2(float hi, float lo) {
    unsigned u; asm("cvt.rn.bf16x2.f32 %0, %1, %2;" : "=r"(u) : "f"(hi), "f"(lo));
    return u;
}
// one packed bf16x2 -> f32x2 {lo<<16, hi&0xFFFF0000}
__device__ __forceinline__ ull bf2_f32x2(unsigned u) {
    ull r;
    asm("{\n\t.reg .b32 lo, hi;\n\t"
        "shl.b32 lo, %1, 16;\n\t"
        "and.b32 hi, %1, 0xFFFF0000;\n\t"
        "mov.b64 %0, {lo, hi};\n\t}"
        : "=l"(r) : "r"(u));
    return r;
}

__global__ __launch_bounds__(512, 2)
void soft_ncuts_main(const float* __restrict__ batch, const float* __restrict__ preds) {
    extern __shared__ char smem_raw[];
    ull*   sP0 = (ull*)smem_raw;           // classes 0-3 as 2x bf16x2
    ull*   sP1 = sP0 + NPAD;               // classes 4-7
    float* sI  = (float*)(sP1 + NPAD);     // intensity fp32

    const int tid = threadIdx.x;
    const int b   = blockIdx.y;
    const int bx  = blockIdx.x;            // 0..63
    const int ox  = (bx >> 3) * 4;
    const int oy  = (bx & 7) * 4;

    const float* batchb = batch + b * 32768;
    const float* predsb = preds + (b * 8) * 32768;

    // ---- stage padded 10x10x38 tile; out-of-volume = EPS ----
    for (int v = tid; v < NPAD; v += 512) {
        int px = v / (TPY * TPZ);
        int r  = v - px * (TPY * TPZ);
        int py = r / TPZ;
        int pz = r - py * TPZ;
        int gx = ox + px - 3, gy = oy + py - 3, gz = pz - 3;
        bool inb = ((unsigned)gx < 32u) && ((unsigned)gy < 32u) && ((unsigned)gz < 32u);
        int g = gx * 1024 + gy * 32 + gz;
        sI[v] = inb ? batchb[g] : EPSV;
        float p[8];
#pragma unroll
        for (int k = 0; k < 8; k++) p[k] = inb ? predsb[k * 32768 + g] : EPSV;
        unsigned u01 = cvt_bf2(p[1], p[0]);
        unsigned u23 = cvt_bf2(p[3], p[2]);
        unsigned u45 = cvt_bf2(p[5], p[4]);
        unsigned u67 = cvt_bf2(p[7], p[6]);
        ull w0, w1;
        asm("mov.b64 %0, {%1, %2};" : "=l"(w0) : "r"(u01), "r"(u23));
        asm("mov.b64 %0, {%1, %2};" : "=l"(w1) : "r"(u45), "r"(u67));
        sP0[v] = w0;
        sP1[v] = w1;
    }
    __syncthreads();

    // thread -> voxel: lane = z (0..31), warp -> (wx, wy)
    const int lz = tid & 31;
    const int wy = (tid >> 5) & 3;
    const int wx = tid >> 7;
    const int v0 = (wx + 3) * (TPY * TPZ) + (wy + 3) * TPZ + (lz + 3);
    const float I = sI[v0];

    ull acc01 = 0ull, acc23 = 0ull, acc45 = 0ull, acc67 = 0ull;
    float sumw = 0.f;
    const float K2 = -0.014426950408889634f;   // -log2(e)/100
    const float K3 = -0.09016844005556021f;    // -log2(e)/16

#define BODY(DZ)                                                          \
    {                                                                     \
        const int v = vb + (DZ);                                          \
        float dI = I - sI[v];                                             \
        float arg = fmaf(dI * dI, K2, crow);                              \
        if ((DZ) != 0) arg += (float)((DZ) * (DZ)) * K3;                  \
        float a = ex2(arg);                                               \
        sumw += a;                                                        \
        ull a2 = pack2(a);                                                \
        ull q0 = sP0[v], q1 = sP1[v];                                     \
        unsigned ua, ub, uc, ud;                                          \
        asm("mov.b64 {%0, %1}, %2;" : "=r"(ua), "=r"(ub) : "l"(q0));      \
        asm("mov.b64 {%0, %1}, %2;" : "=r"(uc), "=r"(ud) : "l"(q1));      \
        fma2(acc01, a2, bf2_f32x2(ua));                                   \
        fma2(acc23, a2, bf2_f32x2(ub));                                   \
        fma2(acc45, a2, bf2_f32x2(uc));                                   \
        fma2(acc67, a2, bf2_f32x2(ud));                                   \
    }

#pragma unroll 3
    for (int i = 0; i < 21; i++) {          // m = 3 rows
        const int vb = v0 + ROWS.off[i];
        const float crow = ROWS.c[i];
        BODY(-3) BODY(-2) BODY(-1) BODY(0) BODY(1) BODY(2) BODY(3)
    }
#pragma unroll 4
    for (int i = 21; i < 37; i++) {         // m = 2 rows
        const int vb = v0 + ROWS.off[i];
        const float crow = ROWS.c[i];
        BODY(-2) BODY(-1) BODY(0) BODY(1) BODY(2)
    }
#pragma unroll 4
    for (int i = 37; i < 45; i++) {         // m = 1 rows
        const int vb = v0 + ROWS.off[i];
        const float crow = ROWS.c[i];
        BODY(-1) BODY(0) BODY(1)
    }
#undef BODY

    // ---- epilogue: own preds exact fp32 from global ----
    const int gx = ox + wx, gy = oy + wy, gz = lz;
    const int g = gx * 1024 + gy * 32 + gz;
    float q[8];
#pragma unroll
    for (int k = 0; k < 8; k++) q[k] = predsb[k * 32768 + g];

    float ac[8];
    unpack2(acc01, ac[0], ac[1]);
    unpack2(acc23, ac[2], ac[3]);
    unpack2(acc45, ac[4], ac[5]);
    unpack2(acc67, ac[6], ac[7]);

    float c[16];
#pragma unroll
    for (int k = 0; k < 8; k++) {
        c[k]     = ac[k] * q[k];
        c[8 + k] = sumw * q[k];
    }

    __shared__ float sRed[16];
    if (tid < 16) sRed[tid] = 0.f;
    __syncthreads();
#pragma unroll
    for (int j = 0; j < 16; j++) {
        float val = c[j];
#pragma unroll
        for (int o = 16; o; o >>= 1) val += __shfl_xor_sync(0xffffffffu, val, o);
        if ((tid & 31) == 0) atomicAdd(&sRed[j], val);
    }
    __syncthreads();
    if (tid < 16) gPart[(b * 64 + bx) * 16 + tid] = sRed[tid];
}

__global__ void finalize_kernel(float* __restrict__ out) {
    __shared__ float sAV[64];
    int tid = threadIdx.x;
    if (tid < 64) {
        int b = tid >> 4, j = tid & 15;
        float s = 0.f;
        for (int t = 0; t < 64; t++) s += gPart[(b * 64 + t) * 16 + j];
        sAV[tid] = s;
    }
    __syncthreads();
    if (tid < 4) {
        float s = 0.f;
#pragma unroll
        for (int k = 0; k < 8; k++) s += sAV[tid * 16 + k] / sAV[tid * 16 + 8 + k];
        out[tid] = 8.f - s;
    }
}

extern "C" void kernel_launch(void* const* d_in, const int* in_sizes, int n_in,
                              void* d_out, int out_size) {
    const float* batch = (const float*)d_in[0];
    const float* preds = (const float*)d_in[1];
    float* out = (float*)d_out;

    cudaFuncSetAttribute(soft_ncuts_main, cudaFuncAttributeMaxDynamicSharedMemorySize,
                         SMEM_BYTES);

    dim3 grid(64, 4);
    soft_ncuts_main<<<grid, 512, SMEM_BYTES>>>(batch, preds);
    finalize_kernel<<<1, 64>>>(out);
}

// round 4
// speedup vs baseline: 2.4409x; 1.2209x over previous
#include <cuda_runtime.h>

// SoftNCutsLoss: B=4, K=8, 32^3, radius 4 -> 251 nonzero window offsets.
// Tile 4x4x32 (z full extent), 512 threads, warp = 32 consecutive z (conflict-free).
// Preds in smem as 8 x fp16 (one LDS.128/offset), HFMA2 accumulation with
// chunked flush to fp32. aff = ex2(dI^2*K2 + d2*K3).

#define EPSV 2.2204460492503131e-16f
#define TPX 10
#define TPY 10
#define TPZ 38
#define NPAD (TPX * TPY * TPZ)      // 3800
#define SMEM_BYTES (NPAD * 16 + NPAD * 4)

__device__ float gPart[256 * 16];   // per-CTA partials: [cta][0..7]=A, [8..15]=V

// row table: (dx,dy) offsets grouped by dz-extent (m=3: 21 rows, m=2: 16, m=1: 8)
struct RowTab {
    int   off[45];
    float c[45];
};
__host__ __device__ constexpr RowTab make_rows() {
    RowTab t{};
    const float K3 = -0.09016844005556021f;  // -log2(e)/16
    int idx = 0;
    for (int want = 3; want >= 1; want--) {
        for (int dx = -3; dx <= 3; dx++)
            for (int dy = -3; dy <= 3; dy++) {
                int r2 = 16 - dx * dx - dy * dy;
                int m = 0;
                if (r2 >= 10) m = 3;
                else if (r2 >= 5) m = 2;
                else if (r2 >= 2) m = 1;
                else continue;
                if (m != want) continue;
                t.off[idx] = dx * (TPY * TPZ) + dy * TPZ;
                t.c[idx] = (float)(dx * dx + dy * dy) * K3;
                idx++;
            }
    }
    return t;
}
__constant__ RowTab ROWS = make_rows();

__device__ __forceinline__ float ex2(float x) {
    float r; asm("ex2.approx.f32 %0, %1;" : "=f"(r) : "f"(x)); return r;
}
__device__ __forceinline__ unsigned cvt_h2(float hi, float lo) {
    unsigned u; asm("cvt.rn.f16x2.f32 %0, %1, %2;" : "=r"(u) : "f"(hi), "f"(lo));
    return u;
}
__device__ __forceinline__ unsigned pack_h2(float a) {
    unsigned u; asm("cvt.rn.f16x2.f32 %0, %1, %1;" : "=r"(u) : "f"(a));
    return u;
}
__device__ __forceinline__ void hfma2(unsigned& acc, unsigned a, unsigned b) {
    asm("fma.rn.f16x2 %0, %1, %2, %0;" : "+r"(acc) : "r"(a), "r"(b));
}
__device__ __forceinline__ void flush_h2(unsigned& h, float& f0, float& f1) {
    float a, b;
    asm("{\n\t.reg .b16 l, m;\n\t"
        "mov.b32 {l, m}, %2;\n\t"
        "cvt.f32.f16 %0, l;\n\t"
        "cvt.f32.f16 %1, m;\n\t}"
        : "=f"(a), "=f"(b) : "r"(h));
    f0 += a; f1 += b; h = 0u;
}

__global__ __launch_bounds__(512, 2)
void soft_ncuts_main(const float* __restrict__ batch, const float* __restrict__ preds) {
    extern __shared__ char smem_raw[];
    uint4* sP = (uint4*)smem_raw;          // 8 classes as 4 x f16x2 (16B/voxel)
    float* sI = (float*)(sP + NPAD);       // intensity fp32

    const int tid = threadIdx.x;
    const int b   = blockIdx.y;
    const int bx  = blockIdx.x;            // 0..63
    const int ox  = (bx >> 3) * 4;
    const int oy  = (bx & 7) * 4;

    const float* batchb = batch + b * 32768;
    const float* predsb = preds + (b * 8) * 32768;

    // ---- stage padded 10x10x38 tile; out-of-volume = EPS ----
    for (int v = tid; v < NPAD; v += 512) {
        int px = v / (TPY * TPZ);
        int r  = v - px * (TPY * TPZ);
        int py = r / TPZ;
        int pz = r - py * TPZ;
        int gx = ox + px - 3, gy = oy + py - 3, gz = pz - 3;
        bool inb = ((unsigned)gx < 32u) && ((unsigned)gy < 32u) && ((unsigned)gz < 32u);
        int g = gx * 1024 + gy * 32 + gz;
        sI[v] = inb ? batchb[g] : EPSV;
        float p[8];
#pragma unroll
        for (int k = 0; k < 8; k++) p[k] = inb ? predsb[k * 32768 + g] : EPSV;
        uint4 w;
        w.x = cvt_h2(p[1], p[0]);   // lo = class0, hi = class1
        w.y = cvt_h2(p[3], p[2]);
        w.z = cvt_h2(p[5], p[4]);
        w.w = cvt_h2(p[7], p[6]);
        sP[v] = w;
    }
    __syncthreads();

    // thread -> voxel: lane = z (0..31), warp -> (wx, wy)
    const int lz = tid & 31;
    const int wy = (tid >> 5) & 3;
    const int wx = tid >> 7;
    const int v0 = (wx + 3) * (TPY * TPZ) + (wy + 3) * TPZ + (lz + 3);
    const float I = sI[v0];

    unsigned h0 = 0u, h1 = 0u, h2a = 0u, h3 = 0u;   // fp16x2 accums (chunked)
    float f[8];
#pragma unroll
    for (int k = 0; k < 8; k++) f[k] = 0.f;
    float sumw = 0.f;
    const float K2 = -0.014426950408889634f;   // -log2(e)/100
    const float K3 = -0.09016844005556021f;    // -log2(e)/16

#define FLUSH()                                         \
    {                                                   \
        flush_h2(h0, f[0], f[1]);                       \
        flush_h2(h1, f[2], f[3]);                       \
        flush_h2(h2a, f[4], f[5]);                      \
        flush_h2(h3, f[6], f[7]);                       \
    }

#define BODY(DZ)                                                           \
    {                                                                      \
        const int v = vb + (DZ);                                           \
        float dI = I - sI[v];                                              \
        float a = ex2(fmaf(dI * dI, K2, crow + (float)((DZ) * (DZ)) * K3));\
        sumw += a;                                                         \
        unsigned a2 = pack_h2(a);                                          \
        uint4 q = sP[v];                                                   \
        hfma2(h0, a2, q.x);                                                \
        hfma2(h1, a2, q.y);                                                \
        hfma2(h2a, a2, q.z);                                               \
        hfma2(h3, a2, q.w);                                                \
    }

#pragma unroll 3
    for (int i = 0; i < 21; i++) {          // m = 3 rows (7 offsets each)
        const int vb = v0 + ROWS.off[i];
        const float crow = ROWS.c[i];
        BODY(-3) BODY(-2) BODY(-1) BODY(0) BODY(1) BODY(2) BODY(3)
        if (i % 3 == 2) FLUSH()             // every 21 adds
    }
#pragma unroll 4
    for (int i = 21; i < 37; i++) {         // m = 2 rows (5 offsets each)
        const int vb = v0 + ROWS.off[i];
        const float crow = ROWS.c[i];
        BODY(-2) BODY(-1) BODY(0) BODY(1) BODY(2)
        if ((i - 21) % 4 == 3) FLUSH()      // every 20 adds
    }
#pragma unroll
    for (int i = 37; i < 45; i++) {         // m = 1 rows (3 offsets each)
        const int vb = v0 + ROWS.off[i];
        const float crow = ROWS.c[i];
        BODY(-1) BODY(0) BODY(1)
    }
    FLUSH()                                 // last 24 adds
#undef BODY
#undef FLUSH

    // ---- epilogue: own preds exact fp32 from global ----
    const int gx = ox + wx, gy = oy + wy, gz = lz;
    const int g = gx * 1024 + gy * 32 + gz;
    float q[8];
#pragma unroll
    for (int k = 0; k < 8; k++) q[k] = predsb[k * 32768 + g];

    float c[16];
#pragma unroll
    for (int k = 0; k < 8; k++) {
        c[k]     = f[k] * q[k];
        c[8 + k] = sumw * q[k];
    }

    __shared__ float sRed[16];
    if (tid < 16) sRed[tid] = 0.f;
    __syncthreads();
#pragma unroll
    for (int j = 0; j < 16; j++) {
        float val = c[j];
#pragma unroll
        for (int o = 16; o; o >>= 1) val += __shfl_xor_sync(0xffffffffu, val, o);
        if ((tid & 31) == 0) atomicAdd(&sRed[j], val);
    }
    __syncthreads();
    if (tid < 16) gPart[(b * 64 + bx) * 16 + tid] = sRed[tid];
}

__global__ void finalize_kernel(float* __restrict__ out) {
    __shared__ float sAV[64];
    const int tid = threadIdx.x;            // 1024 threads
    if (tid < 64) sAV[tid] = 0.f;
    __syncthreads();
    const int b  = tid >> 8;                // 4
    const int j  = (tid >> 4) & 15;         // 16
    const int ch = tid & 15;                // 16 chunks of 4 CTAs
    float s = 0.f;
#pragma unroll
    for (int t = 0; t < 4; t++)
        s += gPart[(b * 64 + ch * 4 + t) * 16 + j];
    atomicAdd(&sAV[b * 16 + j], s);
    __syncthreads();
    if (tid < 4) {
        float s2 = 0.f;
#pragma unroll
        for (int k = 0; k < 8; k++) s2 += sAV[tid * 16 + k] / sAV[tid * 16 + 8 + k];
        out[tid] = 8.f - s2;
    }
}

extern "C" void kernel_launch(void* const* d_in, const int* in_sizes, int n_in,
                              void* d_out, int out_size) {
    const float* batch = (const float*)d_in[0];
    const float* preds = (const float*)d_in[1];
    float* out = (float*)d_out;

    cudaFuncSetAttribute(soft_ncuts_main, cudaFuncAttributeMaxDynamicSharedMemorySize,
                         SMEM_BYTES);

    dim3 grid(64, 4);
    soft_ncuts_main<<<grid, 512, SMEM_BYTES>>>(batch, preds);
    finalize_kernel<<<1, 1024>>>(out);
}

// round 5
// speedup vs baseline: 2.7024x; 1.1071x over previous
#include <cuda_runtime.h>

// SoftNCutsLoss: B=4, K=8, 32^3, radius 4 -> 251 nonzero offsets per voxel.
// Tile 4x4x32, 256 threads; each thread owns 2 voxels (y and y+1) so the
// neighbor pred/intensity loads are shared (union rows: 50, bodies: 296).
// Preds in smem fp16x4 pairs (LDS.128), f16x2 exp path, HFMA2 accumulation
// with chunked flush to fp32. Finalize fused via last-CTA reduction.

#define EPSV 2.2204460492503131e-16f
#define TPX 10
#define TPY 10
#define TPZ 38
#define NPAD (TPX * TPY * TPZ)      // 3800
#define SMEM_BYTES (NPAD * 16 + NPAD * 4)

typedef unsigned uu;

__device__ float gPart[256 * 16];   // per-CTA partials [cta][0..7]=A, [8..15]=V
__device__ unsigned gCount;         // zero-initialized; last CTA resets it

__device__ __forceinline__ float ex2f(float x) {
    float r; asm("ex2.approx.f32 %0, %1;" : "=f"(r) : "f"(x)); return r;
}
__device__ __forceinline__ uu cvt_h2(float hi, float lo) {
    uu u; asm("cvt.rn.f16x2.f32 %0, %1, %2;" : "=r"(u) : "f"(hi), "f"(lo));
    return u;
}
__device__ __forceinline__ uu ex2_h2(uu x) {
    uu r; asm("ex2.approx.f16x2 %0, %1;" : "=r"(r) : "r"(x)); return r;
}
__device__ __forceinline__ void hfma2(uu& acc, uu a, uu b) {
    asm("fma.rn.f16x2 %0, %1, %2, %0;" : "+r"(acc) : "r"(a), "r"(b));
}
__device__ __forceinline__ void hadd2(uu& acc, uu a) {
    asm("add.rn.f16x2 %0, %0, %1;" : "+r"(acc) : "r"(a));
}
__device__ __forceinline__ uu prmt_lo(uu x) {      // (lo, lo)
    uu r; asm("prmt.b32 %0, %1, %1, 0x1010;" : "=r"(r) : "r"(x)); return r;
}
__device__ __forceinline__ uu prmt_hi(uu x) {      // (hi, hi)
    uu r; asm("prmt.b32 %0, %1, %1, 0x3232;" : "=r"(r) : "r"(x)); return r;
}
__device__ __forceinline__ void flush_h2(uu& h, float& f0, float& f1) {
    float a, b;
    asm("{\n\t.reg .b16 l, m;\n\t"
        "mov.b32 {l, m}, %2;\n\t"
        "cvt.f32.f16 %0, l;\n\t"
        "cvt.f32.f16 %1, m;\n\t}"
        : "=f"(a), "=f"(b) : "r"(h));
    f0 += a; f1 += b; h = 0u;
}

__global__ __launch_bounds__(256, 2)
void soft_ncuts_main(const float* __restrict__ batch, const float* __restrict__ preds,
                     float* __restrict__ out) {
    extern __shared__ char smem_raw[];
    uint4* sP4 = (uint4*)smem_raw;          // 8 classes as 4 x f16x2 (16B/voxel)
    float* sI  = (float*)(sP4 + NPAD);      // intensity fp32

    const int tid = threadIdx.x;
    const int b   = blockIdx.y;
    const int bx  = blockIdx.x;             // 0..63
    const int ox  = (bx >> 3) * 4;
    const int oy  = (bx & 7) * 4;

    const float* batchb = batch + b * 32768;
    const float* predsb = preds + (b * 8) * 32768;

    // ---- stage padded 10x10x38 tile; out-of-volume = EPS ----
    for (int v = tid; v < NPAD; v += 256) {
        int px = v / (TPY * TPZ);
        int r  = v - px * (TPY * TPZ);
        int py = r / TPZ;
        int pz = r - py * TPZ;
        int gx = ox + px - 3, gy = oy + py - 3, gz = pz - 3;
        bool inb = ((unsigned)gx < 32u) && ((unsigned)gy < 32u) && ((unsigned)gz < 32u);
        int g = gx * 1024 + gy * 32 + gz;
        sI[v] = inb ? batchb[g] : EPSV;
        float p[8];
#pragma unroll
        for (int k = 0; k < 8; k++) p[k] = inb ? predsb[k * 32768 + g] : EPSV;
        uint4 w;
        w.x = cvt_h2(p[1], p[0]);
        w.y = cvt_h2(p[3], p[2]);
        w.z = cvt_h2(p[5], p[4]);
        w.w = cvt_h2(p[7], p[6]);
        sP4[v] = w;
    }
    __syncthreads();

    // thread -> 2 voxels: lane = z, warp w: wx = w>>1, y-pair = (w&1)*2
    const int lz = tid & 31;
    const int w  = tid >> 5;                // 0..7
    const int wx = w >> 1;
    const int y0 = (w & 1) * 2;
    const int v0 = (wx + 3) * (TPY * TPZ) + (y0 + 3) * TPZ + (lz + 3);
    const float Ip = sI[v0];
    const float Iq = sI[v0 + TPZ];

    uu hp0 = 0, hp1 = 0, hp2 = 0, hp3 = 0;
    uu hq0 = 0, hq1 = 0, hq2 = 0, hq3 = 0;
    uu hsw = 0;
    float fp[8], fq[8];
#pragma unroll
    for (int k = 0; k < 8; k++) { fp[k] = 0.f; fq[k] = 0.f; }
    float fswp = 0.f, fswq = 0.f;
    const float K2 = -0.014426950408889634f;   // -log2(e)/100
    const float K3 = -0.09016844005556021f;    // -log2(e)/16

#define FLUSHALL()                         \
    {                                      \
        flush_h2(hp0, fp[0], fp[1]);       \
        flush_h2(hp1, fp[2], fp[3]);       \
        flush_h2(hp2, fp[4], fp[5]);       \
        flush_h2(hp3, fp[6], fp[7]);       \
        flush_h2(hq0, fq[0], fq[1]);       \
        flush_h2(hq1, fq[2], fq[3]);       \
        flush_h2(hq2, fq[4], fq[5]);       \
        flush_h2(hq3, fq[6], fq[7]);       \
        flush_h2(hsw, fswp, fswq);         \
    }

#pragma unroll
    for (int dx = -3; dx <= 3; dx++) {
#pragma unroll
        for (int dyr = -3; dyr <= 4; dyr++) {
            const int d2p = dx * dx + dyr * dyr;
            const int d2q = dx * dx + (dyr - 1) * (dyr - 1);
            const bool vp = (dyr <= 3) && (d2p <= 14);
            const bool vq = (dyr >= -2) && (d2q <= 14);
            if (vp || vq) {
                const int mm = ((vp && d2p <= 6) || (vq && d2q <= 6)) ? 3
                             : (((vp && d2p <= 11) || (vq && d2q <= 11)) ? 2 : 1);
                const int vb = v0 + dx * (TPY * TPZ) + dyr * TPZ;
#pragma unroll
                for (int dz = -3; dz <= 3; dz++) {
                    if (dz >= -mm && dz <= mm) {
                        const bool lp = vp && (d2p + dz * dz < 16);
                        const bool lq = vq && (d2q + dz * dz < 16);
                        const int v = vb + dz;
                        const float Iv = sI[v];
                        const uint4 qv = sP4[v];
                        float argp = -1e30f, argq = -1e30f;
                        if (lp) {
                            float dp = Ip - Iv;
                            argp = fmaf(dp * dp, K2, (float)(d2p + dz * dz) * K3);
                        }
                        if (lq) {
                            float dq = Iq - Iv;
                            argq = fmaf(dq * dq, K2, (float)(d2q + dz * dz) * K3);
                        }
                        uu e2 = ex2_h2(cvt_h2(argq, argp));  // lo=a_p, hi=a_q
                        hadd2(hsw, e2);
                        if (lp) {
                            uu a2 = prmt_lo(e2);
                            hfma2(hp0, a2, qv.x); hfma2(hp1, a2, qv.y);
                            hfma2(hp2, a2, qv.z); hfma2(hp3, a2, qv.w);
                        }
                        if (lq) {
                            uu a2 = prmt_hi(e2);
                            hfma2(hq0, a2, qv.x); hfma2(hq1, a2, qv.y);
                            hfma2(hq2, a2, qv.z); hfma2(hq3, a2, qv.w);
                        }
                    }
                }
                if (dyr == -1 || dyr == 2 || dyr == 4) FLUSHALL()
            }
        }
    }
    FLUSHALL()
#undef FLUSHALL

    // ---- epilogue: own preds exact fp32 from global; combine both voxels ----
    const int gp = (ox + wx) * 1024 + (oy + y0) * 32 + lz;
    const int gq = gp + 32;
    float c[16];
#pragma unroll
    for (int k = 0; k < 8; k++) {
        float qp = predsb[k * 32768 + gp];
        float qq = predsb[k * 32768 + gq];
        c[k]     = fp[k] * qp + fq[k] * qq;
        c[8 + k] = fswp * qp + fswq * qq;
    }

    __shared__ float sRed[16];
    if (tid < 16) sRed[tid] = 0.f;
    __syncthreads();
#pragma unroll
    for (int j = 0; j < 16; j++) {
        float val = c[j];
#pragma unroll
        for (int o = 16; o; o >>= 1) val += __shfl_xor_sync(0xffffffffu, val, o);
        if ((tid & 31) == 0) atomicAdd(&sRed[j], val);
    }
    __syncthreads();
    if (tid < 16) gPart[(b * 64 + bx) * 16 + tid] = sRed[tid];
    __syncthreads();

    // ---- fused finalize: last CTA reduces all partials ----
    __shared__ unsigned sLast;
    if (tid == 0) {
        __threadfence();
        unsigned t = atomicAdd(&gCount, 1u);
        sLast = (t == 255u) ? 1u : 0u;
    }
    __syncthreads();
    if (sLast) {
        __shared__ float sAV[64];
        if (tid < 64) sAV[tid] = 0.f;
        __syncthreads();
        const int bb = tid >> 6;            // 4
        const int jj = (tid >> 2) & 15;     // 16
        const int ch = tid & 3;             // 4 chunks of 16 CTAs
        float s = 0.f;
#pragma unroll
        for (int t2 = 0; t2 < 16; t2++)
            s += __ldcg(&gPart[(bb * 64 + ch * 16 + t2) * 16 + jj]);
        atomicAdd(&sAV[bb * 16 + jj], s);
        __syncthreads();
        if (tid < 4) {
            float s2 = 0.f;
#pragma unroll
            for (int k = 0; k < 8; k++)
                s2 += sAV[tid * 16 + k] / sAV[tid * 16 + 8 + k];
            out[tid] = 8.f - s2;
        }
        if (tid == 0) gCount = 0u;
    }
}

extern "C" void kernel_launch(void* const* d_in, const int* in_sizes, int n_in,
                              void* d_out, int out_size) {
    const float* batch = (const float*)d_in[0];
    const float* preds = (const float*)d_in[1];
    float* out = (float*)d_out;

    cudaFuncSetAttribute(soft_ncuts_main, cudaFuncAttributeMaxDynamicSharedMemorySize,
                         SMEM_BYTES);

    dim3 grid(64, 4);
    soft_ncuts_main<<<grid, 256, SMEM_BYTES>>>(batch, preds, out);
}